// round 13
// baseline (speedup 1.0000x reference)
#include <cuda_runtime.h>
#include <math.h>
#include <stdint.h>

#define Bsz 128
#define Ssz 1024
#define Hsz 768
#define MAXV 25
#define NTOK 50                 // 2*MAXV
#define S_LEVI (Ssz - NTOK)     // 974
#define H4 (Hsz / 4)            // 192 float4 per row

// ---- GEMM split-K config (R13: one k-tile per block, f32x2 FMA) ----
#define KSPLIT 16               // 768 / 16 = 48 k per block
#define KS   48                 // k per block
#define GTB  32                 // batches per block
#define GTH  64                 // h-outputs per block
#define SWST 68                 // sW row stride (floats), 16B-multiple, padded
#define NTILE ((Bsz / GTB) * (Hsz / GTH))   // 48 output tiles

// Scratch (allocation-free rule: device globals)
__device__ float g_pooled[Bsz * Hsz];
__device__ float g_part[KSPLIT * Bsz * Hsz];   // 6.3 MB partial sums
__device__ int   g_cnt[NTILE];                 // zero-init; reset by last block

__device__ __forceinline__ float warp_sum(float v) {
#pragma unroll
    for (int o = 16; o > 0; o >>= 1) v += __shfl_xor_sync(0xffffffffu, v, o);
    return v;
}

__device__ __forceinline__ uint32_t smem_u32(const void* p) {
    uint32_t a;
    asm("{ .reg .u64 t; cvta.to.shared.u64 t, %1; cvt.u32.u64 %0, t; }"
        : "=r"(a) : "l"(p));
    return a;
}

// pack (f,f) into a 64-bit f32x2 register
#define PACK_DUP(dst, f) \
    asm("mov.b64 %0, {%1, %1};" : "=l"(dst) : "r"(__float_as_uint(f)))

// d.lo += a.lo*b.lo; d.hi += a.hi*b.hi  (two fp32 FMAs, one FFMA2)
#define FMA2(d, a, b) \
    asm("fma.rn.f32x2 %0, %1, %2, %0;" : "+l"(d) : "l"(a), "l"(b))

// Detect verb_count dtype (int64 vs int32) and return v for batch b.
// 64 odd-word samples all zero <=> int64 (values < 25). Warp-collective.
__device__ __forceinline__ int load_verb(const int* __restrict__ verb32,
                                         int b, int lane) {
    int a = verb32[2 * lane + 1];
    int c = verb32[2 * lane + 65];
    unsigned nz = __ballot_sync(0xffffffffu, (a | c) != 0);
    return nz ? verb32[b] : verb32[2 * b];
}

// ---------------------------------------------------------------------------
// Kernel 1: fused masked-attention pooling. One block per batch, 768 threads.
// Active ordinals j in [0,2v): token t = j<v ? j : j-v+MAXV. Inactive rows
// have weight exactly 0 in the reference and are never touched. The
// subject-hidden score term is a per-batch constant over active tokens and
// cancels exactly in softmax; skipped.
// ---------------------------------------------------------------------------
__global__ __launch_bounds__(768, 1)
void pool_kernel(const float* __restrict__ hidden,
                 const int*   __restrict__ verb32,
                 const float* __restrict__ align_w,   // [2H]
                 float*       __restrict__ pooled)    // [B,H]
{
    __shared__ float  s_scores[NTOK];     // by active ordinal j
    __shared__ float  s_wact[NTOK];       // weight of ordinal j
    __shared__ float4 s_part[4][H4];      // 12 KB cross-group pooling partials

    const int b    = blockIdx.x;
    const int tid  = threadIdx.x;
    const int warp = tid >> 5;
    const int lane = tid & 31;

    const int v    = load_verb(verb32, b, lane);   // warp-uniform
    const int nact = 2 * v;

    if (tid < NTOK) s_scores[tid] = -INFINITY;
    __syncthreads();

    const float* __restrict__ bbase = hidden + ((size_t)b * Ssz + S_LEVI) * Hsz;
    const float4* __restrict__ base4 = (const float4*)bbase;
    const float4* __restrict__ w4    = (const float4*)(align_w + Hsz);

    // --- pass 1: scores, warp per active ordinal (24 warps, <=2 rounds) ---
    for (int j = warp; j < nact; j += 24) {
        const int t = (j < v) ? j : (j - v + MAXV);
        const float4* row4 = base4 + (size_t)t * H4;
        float4 a = make_float4(0.f, 0.f, 0.f, 0.f);
#pragma unroll
        for (int i = 0; i < 6; i++) {
            float4 hv = row4[lane + i * 32];
            float4 wv = w4[lane + i * 32];
            a.x = fmaf(hv.x, wv.x, a.x);
            a.y = fmaf(hv.y, wv.y, a.y);
            a.z = fmaf(hv.z, wv.z, a.z);
            a.w = fmaf(hv.w, wv.w, a.w);
        }
        float s = warp_sum((a.x + a.y) + (a.z + a.w));
        if (lane == 0) s_scores[j] = s;
    }
    __syncthreads();

    // --- pass 2: softmax over ordinals (warp 0) ---
    if (warp == 0) {
        float a  = (lane < NTOK)      ? s_scores[lane]      : -INFINITY;
        float b2 = (lane + 32 < NTOK) ? s_scores[lane + 32] : -INFINITY;
        float m = fmaxf(a, b2);
#pragma unroll
        for (int o = 16; o > 0; o >>= 1)
            m = fmaxf(m, __shfl_xor_sync(0xffffffffu, m, o));
        if (!isfinite(m)) m = 0.f;
        float e1 = (a  > -INFINITY) ? expf(a  - m) : 0.f;
        float e2 = (b2 > -INFINITY) ? expf(b2 - m) : 0.f;
        float denom = warp_sum(e1 + e2);
        float inv = (denom > 0.f) ? (1.f / fmaxf(denom, 1e-30f)) : 0.f;
        if (lane < NTOK)      s_wact[lane]      = e1 * inv;
        if (lane + 32 < NTOK) s_wact[lane + 32] = e2 * inv;
    }
    __syncthreads();

    // --- pass 3: pooled, (4 token-groups x 192 h-chunks) then smem reduce ---
    {
        const int grp = tid / H4;     // 0..3
        const int h4  = tid % H4;     // 0..191
        float4 acc = make_float4(0.f, 0.f, 0.f, 0.f);
#pragma unroll 2
        for (int j = grp; j < nact; j += 4) {
            const int t = (j < v) ? j : (j - v + MAXV);
            const float w = s_wact[j];
            float4 hv = base4[(size_t)t * H4 + h4];
            acc.x = fmaf(w, hv.x, acc.x);
            acc.y = fmaf(w, hv.y, acc.y);
            acc.z = fmaf(w, hv.z, acc.z);
            acc.w = fmaf(w, hv.w, acc.w);
        }
        s_part[grp][h4] = acc;
    }
    __syncthreads();

    if (tid < H4) {
        float4 p0 = s_part[0][tid], p1 = s_part[1][tid];
        float4 p2 = s_part[2][tid], p3 = s_part[3][tid];
        float4 r;
        r.x = (p0.x + p1.x) + (p2.x + p3.x);
        r.y = (p0.y + p1.y) + (p2.y + p3.y);
        r.z = (p0.z + p1.z) + (p2.z + p3.z);
        r.w = (p0.w + p1.w) + (p2.w + p3.w);
        ((float4*)pooled)[(size_t)b * H4 + tid] = r;
    }
}

// ---------------------------------------------------------------------------
// Kernel 2: split-K GEMM, one 32b x 64h x 48k tile per block, grid
// (12,4,16)=768 blocks, 128 threads, 4b x 4h per-thread microtile computed
// with packed fma.rn.f32x2 (FFMA2). Fused deterministic last-block
// reduction + bias + tanh (counter self-reset for graph replay).
// ---------------------------------------------------------------------------
__global__ __launch_bounds__(128, 4)
void gemm_fused(const float* __restrict__ P,     // [B,H] pooled
                const float* __restrict__ W,     // [H,H] out_w (k contiguous)
                const float* __restrict__ bias,  // [H]
                float*       __restrict__ part,  // [KSPLIT,B,H] scratch
                float*       __restrict__ out)   // [B,H]
{
    __shared__ __align__(16) float sP[KS][GTB + 1];   // k-major, padded: 6.3 KB
    __shared__ __align__(16) float sW[KS][SWST];      // k-major, padded: 13.1 KB
    __shared__ int s_last;

    const int tid  = threadIdx.x;
    const int h0   = blockIdx.x * GTH;
    const int b0   = blockIdx.y * GTB;
    const int ks0  = blockIdx.z * KS;
    const int tileId = blockIdx.y * gridDim.x + blockIdx.x;

    // --- load P tile 32 x 48 (3 float4/thread), transpose to k-major ---
    {
        const int pr = tid >> 2, fc = tid & 3;
        const float* src = &P[(size_t)(b0 + pr) * Hsz + ks0];
#pragma unroll
        for (int i = 0; i < 3; i++) {
            const int kq = fc + 4 * i;
            float4 vv = *(const float4*)&src[kq * 4];
            sP[kq * 4 + 0][pr] = vv.x;
            sP[kq * 4 + 1][pr] = vv.y;
            sP[kq * 4 + 2][pr] = vv.z;
            sP[kq * 4 + 3][pr] = vv.w;
        }
    }
    // --- load W tile 64 x 48 (6 float4/thread), transpose to k-major ---
    {
        const int hh = tid >> 1, half = tid & 1;
        const float* src = &W[(size_t)(h0 + hh) * Hsz + ks0];
#pragma unroll
        for (int i = 0; i < 6; i++) {
            const int kq = half * 6 + i;
            float4 vv = *(const float4*)&src[kq * 4];
            sW[kq * 4 + 0][hh] = vv.x;
            sW[kq * 4 + 1][hh] = vv.y;
            sW[kq * 4 + 2][hh] = vv.z;
            sW[kq * 4 + 3][hh] = vv.w;
        }
    }
    __syncthreads();

    // --- compute: rows {r, r+8, r+16, r+24}, cols h0 + c4*4 .. +3 ---
    const int r  = tid >> 4;     // 0..7
    const int c4 = tid & 15;     // 0..15
    const uint32_t swaddr = smem_u32(&sW[0][c4 * 4]);

    unsigned long long acc[8];   // [row j][h-pair 0/1] as f32x2
#pragma unroll
    for (int i = 0; i < 8; i++) acc[i] = 0ull;   // (+0.0f, +0.0f)

#pragma unroll
    for (int k = 0; k < KS; k++) {
        float p0 = sP[k][r];
        float p1 = sP[k][r + 8];
        float p2 = sP[k][r + 16];
        float p3 = sP[k][r + 24];
        unsigned long long w01, w23;
        asm("ld.shared.v2.u64 {%0, %1}, [%2];"
            : "=l"(w01), "=l"(w23) : "r"(swaddr + k * (SWST * 4)));
        unsigned long long pp0, pp1, pp2, pp3;
        PACK_DUP(pp0, p0); PACK_DUP(pp1, p1);
        PACK_DUP(pp2, p2); PACK_DUP(pp3, p3);
        FMA2(acc[0], pp0, w01); FMA2(acc[1], pp0, w23);
        FMA2(acc[2], pp1, w01); FMA2(acc[3], pp1, w23);
        FMA2(acc[4], pp2, w01); FMA2(acc[5], pp2, w23);
        FMA2(acc[6], pp3, w01); FMA2(acc[7], pp3, w23);
    }

    // --- store this split's partials (unpack f32x2 -> float4) ---
    {
        float* base = part + ((size_t)blockIdx.z * Bsz) * Hsz;
#pragma unroll
        for (int j = 0; j < 4; j++) {
            float4 s;
            asm("mov.b64 {%0, %1}, %2;" : "=f"(s.x), "=f"(s.y) : "l"(acc[2 * j]));
            asm("mov.b64 {%0, %1}, %2;" : "=f"(s.z), "=f"(s.w) : "l"(acc[2 * j + 1]));
            *(float4*)&base[(size_t)(b0 + r + 8 * j) * Hsz + h0 + c4 * 4] = s;
        }
    }

    // --- last-block-reduces (threadFenceReduction pattern) ---
    __threadfence();
    if (tid == 0) {
        int old = atomicAdd(&g_cnt[tileId], 1);
        int last = (old == KSPLIT - 1);
        if (last) g_cnt[tileId] = 0;   // reset for next graph replay
        s_last = last;
    }
    __syncthreads();
    if (!s_last) return;

    // reduce this tile: each thread its 4 (b,h4) slots, z in fixed order
    const int hb = h0 + c4 * 4;
    const float4 bi = *(const float4*)&bias[hb];
#pragma unroll
    for (int j = 0; j < 4; j++) {
        const size_t off = (size_t)(b0 + r + 8 * j) * Hsz + hb;
        float4 s = make_float4(0.f, 0.f, 0.f, 0.f);
#pragma unroll
        for (int z = 0; z < KSPLIT; z++) {
            float4 pv = *(const float4*)&part[(size_t)z * Bsz * Hsz + off];
            s.x += pv.x; s.y += pv.y; s.z += pv.z; s.w += pv.w;
        }
        float4 o;
        o.x = tanhf(s.x + bi.x);
        o.y = tanhf(s.y + bi.y);
        o.z = tanhf(s.z + bi.z);
        o.w = tanhf(s.w + bi.w);
        *(float4*)&out[off] = o;
    }
}

// ---------------------------------------------------------------------------
extern "C" void kernel_launch(void* const* d_in, const int* in_sizes, int n_in,
                              void* d_out, int out_size)
{
    const float* hidden   = (const float*)d_in[0];
    const int*   verb32   = (const int*)  d_in[1];  // int32 view; dtype auto-detected
    const float* align_w  = (const float*)d_in[3];
    const float* out_w    = (const float*)d_in[5];
    const float* out_b    = (const float*)d_in[6];
    float* out = (float*)d_out;

    float* pooled = nullptr;
    float* part   = nullptr;
    cudaGetSymbolAddress((void**)&pooled, g_pooled);
    cudaGetSymbolAddress((void**)&part,   g_part);

    pool_kernel<<<Bsz, 768>>>(hidden, verb32, align_w, pooled);
    gemm_fused<<<dim3(Hsz / GTH, Bsz / GTB, KSPLIT), 128>>>(pooled, out_w,
                                                            out_b, part, out);
}